// round 5
// baseline (speedup 1.0000x reference)
#include <cuda_runtime.h>

// Problem constants (fixed by setup_inputs)
#define B_ 16
#define A_ 9
#define H_ 128
#define W_ 128
#define S_ 2048.0f
// sigmoid(d) > 0.7  <=>  d > ln(7/3)
#define LOGIT_THRESH 0.84729786038720363f

#define TPB 128

// Single kernel. Per block:
//  - inline anchor gather: thread tid loads anchor row a*tid*129 (2 aligned
//    LDG.64), stores transposed into sAnc. Divergent, but once per block and
//    fully absorbed under the DRAM-write-bound envelope (L1/issue slack).
//  - 6 x LDG.128 vectorized inputs per thread (4 consecutive w positions)
//  - results packed to float4 in smem, block copy-out fully coalesced with
//    streaming stores (keep the L2-resident inputs unevicted).
__global__ __launch_bounds__(TPB) void proposal_kernel(
    const float* __restrict__ cla,
    const float* __restrict__ reg,
    const float* __restrict__ anchor,
    float* __restrict__ out)
{
    // Output staging: TPB threads x 9 float4 slots, output-linear layout.
    __shared__ float4 sOut[TPB * 9];          // 18432 B
    // Anchor row for this block's `a`, transposed: row w at slot (w&3)*32 + (w>>2).
    __shared__ float4 sAnc[W_];               // 2048 B

    const int WQ  = W_ / 4;         // 32
    const int HW4 = (H_ * W_) / 4;  // 4096 float4 per channel plane

    int tid = threadIdx.x;
    int t = blockIdx.x * TPB + tid;
    int wq = t & (WQ - 1);                    // == tid & 31
    int h  = (t / WQ) & (H_ - 1);
    int a  = (t / (WQ * H_)) % A_;            // uniform within a block
    int b  =  t / (WQ * H_ * A_);
    int w0 = wq * 4;

    // Inline anchor gather: row idx[a, w=tid] = a * tid * (W+1).
    // p+2 is 8B-aligned (row*6 even), p+4 likewise -> two LDG.64.
    {
        long row = (long)a * tid * (W_ + 1);
        const float* p = anchor + row * 6;
        float2 acxy = *(const float2*)(p + 2);   // acx, acy
        float2 awh  = *(const float2*)(p + 4);   // aw, ah
        sAnc[(tid & 3) * 32 + (tid >> 2)] =
            make_float4(acxy.x, acxy.y, awh.x, awh.y);
    }

    int sp4 = (h * W_ + w0) >> 2;

    const float4* cla4 = (const float4*)cla;
    const float4* reg4 = (const float4*)reg;

    int cbase = (b * 2 * A_ + 2 * a) * HW4 + sp4;
    float4 v_c0 = cla4[cbase];
    float4 v_c1 = cla4[cbase + HW4];

    int rbase = (b * 4 * A_ + 4 * a) * HW4 + sp4;
    float4 v_tx = reg4[rbase + 0 * HW4];
    float4 v_ty = reg4[rbase + 1 * HW4];
    float4 v_tw = reg4[rbase + 2 * HW4];
    float4 v_th = reg4[rbase + 3 * HW4];

    float c0a[4] = {v_c0.x, v_c0.y, v_c0.z, v_c0.w};
    float c1a[4] = {v_c1.x, v_c1.y, v_c1.z, v_c1.w};
    float txa[4] = {v_tx.x, v_tx.y, v_tx.z, v_tx.w};
    float tya[4] = {v_ty.x, v_ty.y, v_ty.z, v_ty.w};
    float twa[4] = {v_tw.x, v_tw.y, v_tw.z, v_tw.w};
    float tha[4] = {v_th.x, v_th.y, v_th.z, v_th.w};

    __syncthreads();   // anchor staging visible

    float4* my = sOut + tid * 9;   // slot stride 9 float4 = 36 words: conflict-free STS.128

    float f[4][9];
    #pragma unroll
    for (int i = 0; i < 4; i++) {
        // transposed read: row (4*wq + i) lives at slot i*32 + wq -> conflict-free LDS.128
        float4 anc = sAnc[i * 32 + wq];
        float acx = anc.x, acy = anc.y, aw = anc.z, ah = anc.w;

        float cxn = fmaf(txa[i], aw, acx);
        float cyn = fmaf(tya[i], ah, acy);
        float wvn = expf(twa[i]) * aw;
        float hvn = expf(tha[i]) * ah;

        float ltxn = cxn - 0.5f * wvn;
        float ltyn = cyn - 0.5f * hvn;
        float rbxn = cxn + 0.5f * wvn;
        float rbyn = cyn + 0.5f * hvn;

        // fg > 0.7  <=>  (c1 - c0) > ln(7/3)
        bool valid = ((c1a[i] - c0a[i]) > LOGIT_THRESH)
                     && (ltxn >= 0.0f) && (ltyn >= 0.0f)
                     && (rbxn <= 1.0f) && (rbyn <= 1.0f);
        float m = valid ? 1.0f : 0.0f;

        f[i][0] = (ltxn * S_) * m;
        f[i][1] = (ltyn * S_) * m;
        f[i][2] = (rbxn * S_) * m;
        f[i][3] = (rbyn * S_) * m;
        f[i][4] = cxn * m;
        f[i][5] = cyn * m;
        f[i][6] = wvn * m;
        f[i][7] = hvn * m;
        f[i][8] = m;
    }

    // Pack 4x9 floats into 9 float4 smem slots (output-linear order).
    my[0] = make_float4(f[0][0], f[0][1], f[0][2], f[0][3]);
    my[1] = make_float4(f[0][4], f[0][5], f[0][6], f[0][7]);
    my[2] = make_float4(f[0][8], f[1][0], f[1][1], f[1][2]);
    my[3] = make_float4(f[1][3], f[1][4], f[1][5], f[1][6]);
    my[4] = make_float4(f[1][7], f[1][8], f[2][0], f[2][1]);
    my[5] = make_float4(f[2][2], f[2][3], f[2][4], f[2][5]);
    my[6] = make_float4(f[2][6], f[2][7], f[2][8], f[3][0]);
    my[7] = make_float4(f[3][1], f[3][2], f[3][3], f[3][4]);
    my[8] = make_float4(f[3][5], f[3][6], f[3][7], f[3][8]);

    __syncthreads();

    // Coalesced vectorized copy-out: lane-consecutive float4, streaming stores.
    float4* o4 = (float4*)out + (size_t)blockIdx.x * (TPB * 9);
    #pragma unroll
    for (int it = 0; it < 9; it++) {
        int s = tid + it * TPB;
        __stcs(o4 + s, sOut[s]);   // LDS.128 conflict-free, STG.128 512B/warp
    }
}

extern "C" void kernel_launch(void* const* d_in, const int* in_sizes, int n_in,
                              void* d_out, int out_size) {
    const float* cla    = (const float*)d_in[0];
    const float* reg    = (const float*)d_in[1];
    const float* anchor = (const float*)d_in[2];
    float* out = (float*)d_out;

    int total_vec = B_ * A_ * H_ * (W_ / 4);   // 589824
    proposal_kernel<<<total_vec / TPB, TPB>>>(cla, reg, anchor, out);
}

// round 6
// speedup vs baseline: 1.2708x; 1.2708x over previous
#include <cuda_runtime.h>

// Problem constants (fixed by setup_inputs)
#define B_ 16
#define A_ 9
#define H_ 128
#define W_ 128
#define S_ 2048.0f
// sigmoid(d) > 0.7  <=>  d > ln(7/3)
#define LOGIT_THRESH 0.84729786038720363f

#define TPB 128

// Precomputed anchor table, (a, w) order: (acx, acy, aw, ah). 18 KB, stays hot
// in L1/L2 during the main kernel. Built by a tiny prologue (the gather
// pattern a*w*129 is lane-divergent; doing it once here instead of per-block
// is worth ~9us -- measured R4 vs R5).
__device__ float4 d_anc_tab[A_ * W_];

__global__ void build_anchor_tab(const float* __restrict__ anchor) {
    int t = blockIdx.x * blockDim.x + threadIdx.x;
    if (t >= A_ * W_) return;
    int a = t / W_;
    int w = t % W_;
    // idx[a, w] = (w*W + w) * a = a * w * (W+1)
    long row = (long)a * w * (W_ + 1);
    const float* p = anchor + row * 6;
    d_anc_tab[t] = make_float4(p[2], p[3], p[4], p[5]);
}

// Main kernel, DRAM-write-bound (~3.5 TB/s on the 85MB output stream):
//  - 6 x LDG.128 vectorized inputs per thread (4 consecutive w positions)
//  - 4 x LDG.128 coalesced, L1-hot anchor-table reads (lane-consecutive)
//  - results packed to float4 in smem (conflict-free STS.128), single barrier,
//    block copy-out fully coalesced with streaming stores.
__global__ __launch_bounds__(TPB) void proposal_kernel(
    const float* __restrict__ cla,
    const float* __restrict__ reg,
    float* __restrict__ out)
{
    // Output staging: TPB threads x 9 float4 slots, output-linear layout.
    __shared__ float4 sOut[TPB * 9];          // 18432 B

    const int WQ  = W_ / 4;         // 32
    const int HW4 = (H_ * W_) / 4;  // 4096 float4 per channel plane

    int tid = threadIdx.x;
    int t = blockIdx.x * TPB + tid;
    int wq = t & (WQ - 1);                    // == tid & 31
    int h  = (t / WQ) & (H_ - 1);
    int a  = (t / (WQ * H_)) % A_;            // uniform within a block
    int b  =  t / (WQ * H_ * A_);
    int w0 = wq * 4;

    int sp4 = (h * W_ + w0) >> 2;

    const float4* cla4 = (const float4*)cla;
    const float4* reg4 = (const float4*)reg;

    int cbase = (b * 2 * A_ + 2 * a) * HW4 + sp4;
    float4 v_c0 = cla4[cbase];
    float4 v_c1 = cla4[cbase + HW4];

    int rbase = (b * 4 * A_ + 4 * a) * HW4 + sp4;
    float4 v_tx = reg4[rbase + 0 * HW4];
    float4 v_ty = reg4[rbase + 1 * HW4];
    float4 v_tw = reg4[rbase + 2 * HW4];
    float4 v_th = reg4[rbase + 3 * HW4];

    // Anchor entries: 4 consecutive float4s, lane-consecutive across the warp
    // (4 x 512B coalesced LDG.128 from the 18KB hot table). No smem, no barrier.
    const float4* tab = d_anc_tab + a * W_ + w0;
    float4 anc0 = tab[0];
    float4 anc1 = tab[1];
    float4 anc2 = tab[2];
    float4 anc3 = tab[3];

    float c0a[4] = {v_c0.x, v_c0.y, v_c0.z, v_c0.w};
    float c1a[4] = {v_c1.x, v_c1.y, v_c1.z, v_c1.w};
    float txa[4] = {v_tx.x, v_tx.y, v_tx.z, v_tx.w};
    float tya[4] = {v_ty.x, v_ty.y, v_ty.z, v_ty.w};
    float twa[4] = {v_tw.x, v_tw.y, v_tw.z, v_tw.w};
    float tha[4] = {v_th.x, v_th.y, v_th.z, v_th.w};
    float4 anca[4] = {anc0, anc1, anc2, anc3};

    float4* my = sOut + tid * 9;   // slot stride 9 float4 = 36 words: conflict-free STS.128

    float f[4][9];
    #pragma unroll
    for (int i = 0; i < 4; i++) {
        float acx = anca[i].x, acy = anca[i].y, aw = anca[i].z, ah = anca[i].w;

        float cxn = fmaf(txa[i], aw, acx);
        float cyn = fmaf(tya[i], ah, acy);
        float wvn = expf(twa[i]) * aw;
        float hvn = expf(tha[i]) * ah;

        float ltxn = cxn - 0.5f * wvn;
        float ltyn = cyn - 0.5f * hvn;
        float rbxn = cxn + 0.5f * wvn;
        float rbyn = cyn + 0.5f * hvn;

        // fg > 0.7  <=>  (c1 - c0) > ln(7/3)
        bool valid = ((c1a[i] - c0a[i]) > LOGIT_THRESH)
                     && (ltxn >= 0.0f) && (ltyn >= 0.0f)
                     && (rbxn <= 1.0f) && (rbyn <= 1.0f);
        float m = valid ? 1.0f : 0.0f;

        f[i][0] = (ltxn * S_) * m;
        f[i][1] = (ltyn * S_) * m;
        f[i][2] = (rbxn * S_) * m;
        f[i][3] = (rbyn * S_) * m;
        f[i][4] = cxn * m;
        f[i][5] = cyn * m;
        f[i][6] = wvn * m;
        f[i][7] = hvn * m;
        f[i][8] = m;
    }

    // Pack 4x9 floats into 9 float4 smem slots (output-linear order).
    my[0] = make_float4(f[0][0], f[0][1], f[0][2], f[0][3]);
    my[1] = make_float4(f[0][4], f[0][5], f[0][6], f[0][7]);
    my[2] = make_float4(f[0][8], f[1][0], f[1][1], f[1][2]);
    my[3] = make_float4(f[1][3], f[1][4], f[1][5], f[1][6]);
    my[4] = make_float4(f[1][7], f[1][8], f[2][0], f[2][1]);
    my[5] = make_float4(f[2][2], f[2][3], f[2][4], f[2][5]);
    my[6] = make_float4(f[2][6], f[2][7], f[2][8], f[3][0]);
    my[7] = make_float4(f[3][1], f[3][2], f[3][3], f[3][4]);
    my[8] = make_float4(f[3][5], f[3][6], f[3][7], f[3][8]);

    __syncthreads();

    // Coalesced vectorized copy-out: lane-consecutive float4, streaming stores.
    float4* o4 = (float4*)out + (size_t)blockIdx.x * (TPB * 9);
    #pragma unroll
    for (int it = 0; it < 9; it++) {
        int s = tid + it * TPB;
        __stcs(o4 + s, sOut[s]);   // LDS.128 conflict-free, STG.128 512B/warp
    }
}

extern "C" void kernel_launch(void* const* d_in, const int* in_sizes, int n_in,
                              void* d_out, int out_size) {
    const float* cla    = (const float*)d_in[0];
    const float* reg    = (const float*)d_in[1];
    const float* anchor = (const float*)d_in[2];
    float* out = (float*)d_out;

    build_anchor_tab<<<(A_ * W_ + 127) / 128, 128>>>(anchor);

    int total_vec = B_ * A_ * H_ * (W_ / 4);   // 589824
    proposal_kernel<<<total_vec / TPB, TPB>>>(cla, reg, out);
}